// round 2
// baseline (speedup 1.0000x reference)
#include <cuda_runtime.h>

#define T_ 4
#define B_ 16
#define C_ 256
#define N_ 1024
#define CN_ (C_*N_)          // 262144
#define BCN (B_*C_*N_)       // 4194304
#define TBCN (T_*BCN)        // 16777216
#define NBITS (T_*B_*8*N_)   // 524288 words per branch

// Scratch (device globals: allocation-free)
__device__ float    g_y[3][TBCN];     // post-BN pre-LIF activations for q,k,v
__device__ unsigned g_bits[3][NBITS]; // spike bitpack: word at ((t*B+b)*8+h)*N+n, bit d=c%32
__device__ float    g_xa[TBCN];       // attention output (pre-LIF2)
__device__ float    g_xs[TBCN];       // LIF2 spikes (float, input to p-GEMM)
__device__ float    g_yp[TBCN];       // p-GEMM post-BN (pre-LIF3)

// ---------------------------------------------------------------------------
// GEMM + BN:  Y[tb, o, n] = BN( sum_c W[o,c] * X[tb, c, n] + bias[o] )
// Tile: 128x128x8, 256 threads, 8x8 per-thread register tile.
// ---------------------------------------------------------------------------
__global__ __launch_bounds__(256, 2)
void gemm_bn_kernel(const float* __restrict__ Xin, int use_gxs, int ydst,
                    const float* __restrict__ W,
                    const float* __restrict__ bias,
                    const float* __restrict__ gamma,
                    const float* __restrict__ beta,
                    const float* __restrict__ mean,
                    const float* __restrict__ var)
{
    __shared__ float As[8][128];
    __shared__ float Bs[8][128];

    const float* X = use_gxs ? g_xs : Xin;
    float* Y = (ydst < 3) ? g_y[ydst] : g_yp;

    const int tb = blockIdx.z;
    const int m0 = blockIdx.y * 128;
    const int n0 = blockIdx.x * 128;
    const float* Xb = X + (size_t)tb * CN_;
    float* Yb = Y + (size_t)tb * CN_;
    const int tid = threadIdx.x;

    const int la_m = tid >> 1;          // 0..127
    const int la_k = (tid & 1) * 4;     // 0 or 4
    const int lb_k = tid >> 5;          // 0..7
    const int lb_n = (tid & 31) * 4;    // 0..124

    const int tx = tid & 15;            // n-group
    const int ty = tid >> 4;            // m-group

    float acc[8][8];
    #pragma unroll
    for (int i = 0; i < 8; i++)
        #pragma unroll
        for (int j = 0; j < 8; j++) acc[i][j] = 0.f;

    for (int k0 = 0; k0 < C_; k0 += 8) {
        float4 a4 = *(const float4*)(W + (size_t)(m0 + la_m) * C_ + k0 + la_k);
        As[la_k + 0][la_m] = a4.x;
        As[la_k + 1][la_m] = a4.y;
        As[la_k + 2][la_m] = a4.z;
        As[la_k + 3][la_m] = a4.w;
        *(float4*)&Bs[lb_k][lb_n] =
            *(const float4*)(Xb + (size_t)(k0 + lb_k) * N_ + n0 + lb_n);
        __syncthreads();
        #pragma unroll
        for (int k = 0; k < 8; k++) {
            float4 a0 = *(const float4*)&As[k][ty * 8];
            float4 a1 = *(const float4*)&As[k][ty * 8 + 4];
            float4 b0 = *(const float4*)&Bs[k][tx * 8];
            float4 b1 = *(const float4*)&Bs[k][tx * 8 + 4];
            float am[8] = {a0.x, a0.y, a0.z, a0.w, a1.x, a1.y, a1.z, a1.w};
            float bn[8] = {b0.x, b0.y, b0.z, b0.w, b1.x, b1.y, b1.z, b1.w};
            #pragma unroll
            for (int i = 0; i < 8; i++)
                #pragma unroll
                for (int j = 0; j < 8; j++)
                    acc[i][j] += am[i] * bn[j];
        }
        __syncthreads();
    }

    #pragma unroll
    for (int i = 0; i < 8; i++) {
        int o = m0 + ty * 8 + i;
        float sc = gamma[o] * rsqrtf(var[o] + 1e-5f);
        float sh = beta[o] - mean[o] * sc;
        float bi = bias ? bias[o] : 0.f;
        float* yr = Yb + (size_t)o * N_ + n0 + tx * 8;
        float4 v0 = make_float4((acc[i][0] + bi) * sc + sh,
                                (acc[i][1] + bi) * sc + sh,
                                (acc[i][2] + bi) * sc + sh,
                                (acc[i][3] + bi) * sc + sh);
        float4 v1 = make_float4((acc[i][4] + bi) * sc + sh,
                                (acc[i][5] + bi) * sc + sh,
                                (acc[i][6] + bi) * sc + sh,
                                (acc[i][7] + bi) * sc + sh);
        *(float4*)yr = v0;
        *(float4*)(yr + 4) = v1;
    }
}

// ---------------------------------------------------------------------------
// LIF over T (vth=1) for q,k,v + bitpack: bit d of word (t,b,h,n) = spike of
// channel c=h*32+d at spatial n. One thread per (b,h,n), loops d and t.
// ---------------------------------------------------------------------------
__global__ __launch_bounds__(256)
void lif_pack_kernel()
{
    const int proj = blockIdx.y;
    const int idx = blockIdx.x * 256 + threadIdx.x;  // < B*8*N = 131072
    const int n = idx & (N_ - 1);
    const int h = (idx >> 10) & 7;
    const int b = idx >> 13;
    const float* Y = g_y[proj];

    unsigned bits[4] = {0u, 0u, 0u, 0u};
    for (int d = 0; d < 32; d++) {
        const float* p = Y + (size_t)b * CN_ + (size_t)(h * 32 + d) * N_ + n;
        float mem = 0.f;
        #pragma unroll
        for (int t = 0; t < 4; t++) {
            float y = p[(size_t)t * BCN];
            mem += (y - mem) * 0.5f;
            if (mem >= 1.0f) { bits[t] |= (1u << d); mem = 0.f; }
        }
    }
    const int ob = (b * 8 + h) * N_ + n;
    #pragma unroll
    for (int t = 0; t < 4; t++)
        g_bits[proj][t * (B_ * 8 * N_) + ob] = bits[t];
}

// ---------------------------------------------------------------------------
// Write v output: v[t,b,h,n,e] = spike bit e of word (t,b,h,n). Linear idx
// over [T,B,h,N,d] (d fastest) -> word = idx>>5, bit = idx&31. Coalesced.
// ---------------------------------------------------------------------------
__global__ __launch_bounds__(256)
void v_writer_kernel(float* __restrict__ vout)
{
    const int idx = blockIdx.x * 256 + threadIdx.x;
    unsigned w = g_bits[2][idx >> 5];
    vout[idx] = (float)((w >> (idx & 31)) & 1u);
}

// ---------------------------------------------------------------------------
// Per (t,b,h): kv[d][e] = popc-sum over n of k_d(n)&v_e(n); then
// xa[c=h*32+e][n] = 0.125 * sum_d q_d(n) * kv[d][e].
// ---------------------------------------------------------------------------
__global__ __launch_bounds__(256)
void kv_attn_kernel()
{
    __shared__ unsigned qb[1024], kb[1024], vb[1024];
    __shared__ unsigned krow[32][33], vrow[32][33];
    __shared__ float kvm[32][33];

    const int bid = blockIdx.x;    // (t*B+b)*8+h
    const int tid = threadIdx.x;
    const unsigned base = (unsigned)bid * 1024u;

    for (int i = tid; i < 1024; i += 256) {
        qb[i] = g_bits[0][base + i];
        kb[i] = g_bits[1][base + i];
        vb[i] = g_bits[2][base + i];
    }
    __syncthreads();

    // bit-transpose k,v: krow[d][w] has bit j = spike(channel d, n=w*32+j)
    const int d = tid & 31;
    for (int w = tid >> 5; w < 32; w += 8) {
        unsigned rk = 0u, rv = 0u;
        #pragma unroll
        for (int j = 0; j < 32; j++) {
            rk |= ((kb[w * 32 + j] >> d) & 1u) << j;
            rv |= ((vb[w * 32 + j] >> d) & 1u) << j;
        }
        krow[d][w] = rk; vrow[d][w] = rv;
    }
    __syncthreads();

    for (int p = tid; p < 1024; p += 256) {
        int dd = p >> 5, e = p & 31;
        int s = 0;
        #pragma unroll
        for (int w = 0; w < 32; w++)
            s += __popc(krow[dd][w] & vrow[e][w]);
        kvm[dd][e] = (float)s;
    }
    __syncthreads();

    const int tb = bid >> 3, h = bid & 7;
    const int nl = tid & 31;
    for (int e = tid >> 5; e < 32; e += 8) {
        float* out = g_xa + (size_t)tb * CN_ + (size_t)(h * 32 + e) * N_;
        for (int j = 0; j < 32; j++) {
            int n = nl + j * 32;
            unsigned qm = qb[n];
            float s = 0.f;
            if (qm) {
                #pragma unroll
                for (int dd = 0; dd < 32; dd++)
                    if (qm & (1u << dd)) s += kvm[dd][e];
            }
            out[n] = 0.125f * s;
        }
    }
}

// ---------------------------------------------------------------------------
// Generic float LIF over T. src: 0 -> g_xa, 1 -> g_yp. dst: g_xs or out ptr.
// ---------------------------------------------------------------------------
__global__ __launch_bounds__(256)
void lif_f_kernel(int src_sel, float* __restrict__ dst_ptr, int dst_is_ptr, float vth)
{
    const int idx = blockIdx.x * 256 + threadIdx.x;   // < BCN
    const float* Y = src_sel ? g_yp : g_xa;
    float* S = dst_is_ptr ? dst_ptr : g_xs;
    float mem = 0.f;
    #pragma unroll
    for (int t = 0; t < 4; t++) {
        float y = Y[(size_t)t * BCN + idx];
        mem += (y - mem) * 0.5f;
        float s = (mem >= vth) ? 1.0f : 0.0f;
        S[(size_t)t * BCN + idx] = s;
        mem *= (1.0f - s);
    }
}

// ---------------------------------------------------------------------------
extern "C" void kernel_launch(void* const* d_in, const int* in_sizes, int n_in,
                              void* d_out, int out_size)
{
    const float* x  = (const float*)d_in[0];
    // inputs: x, res_attn, {q,k,v}x{w,gamma,beta,mean,var}, p_{w,b,gamma,beta,mean,var}
    const float* qw = (const float*)d_in[2];
    const float* qg = (const float*)d_in[3];
    const float* qb = (const float*)d_in[4];
    const float* qm = (const float*)d_in[5];
    const float* qv = (const float*)d_in[6];
    const float* kw = (const float*)d_in[7];
    const float* kg = (const float*)d_in[8];
    const float* kb = (const float*)d_in[9];
    const float* km = (const float*)d_in[10];
    const float* kv = (const float*)d_in[11];
    const float* vw = (const float*)d_in[12];
    const float* vg = (const float*)d_in[13];
    const float* vb = (const float*)d_in[14];
    const float* vm = (const float*)d_in[15];
    const float* vv = (const float*)d_in[16];
    const float* pw = (const float*)d_in[17];
    const float* pb = (const float*)d_in[18];
    const float* pg = (const float*)d_in[19];
    const float* pbt = (const float*)d_in[20];
    const float* pm = (const float*)d_in[21];
    const float* pv = (const float*)d_in[22];

    float* out  = (float*)d_out;
    float* vout = out + TBCN;

    dim3 ggrid(N_ / 128, C_ / 128, T_ * B_);
    // q, k, v projections -> g_y[0..2]
    gemm_bn_kernel<<<ggrid, 256>>>(x, 0, 0, qw, nullptr, qg, qb, qm, qv);
    gemm_bn_kernel<<<ggrid, 256>>>(x, 0, 1, kw, nullptr, kg, kb, km, kv);
    gemm_bn_kernel<<<ggrid, 256>>>(x, 0, 2, vw, nullptr, vg, vb, vm, vv);

    // LIF + bitpack for all three branches
    lif_pack_kernel<<<dim3((B_ * 8 * N_) / 256, 3), 256>>>();

    // v output
    if (out_size >= 2 * TBCN)
        v_writer_kernel<<<TBCN / 256, 256>>>(vout);

    // kv + attn -> g_xa
    kv_attn_kernel<<<T_ * B_ * 8, 256>>>();

    // LIF(0.5) -> g_xs
    lif_f_kernel<<<BCN / 256, 256>>>(0, nullptr, 0, 0.5f);

    // p projection + bias + BN -> g_yp
    gemm_bn_kernel<<<ggrid, 256>>>(nullptr, 1, 3, pw, pb, pg, pbt, pm, pv);

    // LIF(1.0) -> out
    lif_f_kernel<<<BCN / 256, 256>>>(1, out, 1, 1.0f);
}